// round 15
// baseline (speedup 1.0000x reference)
#include <cuda_runtime.h>
#include <cuda_fp16.h>
#include <math.h>
#include <stdint.h>

// Tree-LSTM, 4-ary, depth 8. E=H=128, A=4. N_NODES=87381, leaves=65536.
// R15: (a) leaf epilogue via shfl_xor gate exchange + 2 parallel staged output
// passes (8 syncs/tile -> 4, no quarter serialization); (b) levels n<=1024 fused
// into one persistent 64-CTA kernel with atomic grid barriers (6 launches -> 1).

#define NN     87381
#define NLEAF  65536

__device__ __half g_Mh[896 * 640];             // inner weight, PERMUTED cp = h*7+g
__device__ float  g_bias[896];                 // inner bias, PERMUTED
__device__ __half g_Mleaf[512 * 128];          // leaf weight, PERMUTED col = h*4+gate
__device__ float  g_bleaf[512];                // leaf bias, PERMUTED
__device__ float  g_cuf[512];
__device__ __half g_emb16[(size_t)NN * 128];
__device__ __half g_h16[(size_t)NN * 128];
__device__ int    g_tbar[8];                   // tail grid-barrier counters

__device__ __forceinline__ float sigf(float x) {
    return __fdividef(1.f, 1.f + __expf(-x));
}
__device__ __forceinline__ float tanh_fast(float x) {
    return 1.f - __fdividef(2.f, __expf(2.f * x) + 1.f);
}
__device__ __forceinline__ void cp16(uint32_t dst, const void* src, uint32_t srcsz) {
    asm volatile("cp.async.ca.shared.global [%0], [%1], 16, %2;"
                 :: "r"(dst), "l"(src), "r"(srcsz));
}
#define CP_COMMIT() asm volatile("cp.async.commit_group;" ::: "memory")
#define CP_WAIT(N)  asm volatile("cp.async.wait_group %0;" :: "n"(N) : "memory")

__device__ __forceinline__ void ldm_x4(uint32_t* r, uint32_t addr) {
    asm volatile("ldmatrix.sync.aligned.m8n8.x4.shared.b16 {%0,%1,%2,%3}, [%4];"
                 : "=r"(r[0]), "=r"(r[1]), "=r"(r[2]), "=r"(r[3]) : "r"(addr));
}
__device__ __forceinline__ void ldm_x2(uint32_t* r, uint32_t addr) {
    asm volatile("ldmatrix.sync.aligned.m8n8.x2.shared.b16 {%0,%1}, [%2];"
                 : "=r"(r[0]), "=r"(r[1]) : "r"(addr));
}
__device__ __forceinline__ void mma16(float* c, const uint32_t* a, const uint32_t* b) {
    asm volatile(
        "mma.sync.aligned.m16n8k16.row.col.f32.f16.f16.f32 "
        "{%0,%1,%2,%3}, {%4,%5,%6,%7}, {%8,%9}, {%0,%1,%2,%3};"
        : "+f"(c[0]), "+f"(c[1]), "+f"(c[2]), "+f"(c[3])
        : "r"(a[0]), "r"(a[1]), "r"(a[2]), "r"(a[3]), "r"(b[0]), "r"(b[1]));
}

// ---------------- prep ----------------
__global__ void prep_M_kernel(const float* __restrict__ W_iou, const float* __restrict__ U_iou,
                              const float* __restrict__ b_iou, const float* __restrict__ b_uiou,
                              const float* __restrict__ W_f,  const float* __restrict__ U_f,
                              const float* __restrict__ b_wf, const float* __restrict__ b_uf) {
    int stride = gridDim.x * blockDim.x;
    int idx = blockIdx.x * blockDim.x + threadIdx.x;
    for (int t = idx; t < 896 * 640; t += stride) {
        int cp = t / 640, k = t - cp * 640;
        int h = cp / 7, g = cp - h * 7;
        float v;
        if (g < 3) {
            int c = g * 128 + h;
            v = (k < 128) ? W_iou[c * 128 + k] : U_iou[c * 512 + (k - 128)];
        } else {
            int cc = (g - 3) * 128 + h;
            v = (k < 128) ? W_f[h * 128 + k] : U_f[cc * 512 + (k - 128)];
        }
        g_Mh[t] = __float2half_rn(v);
    }
    for (int t = idx; t < 512 * 128; t += stride) {
        int c = t >> 7, k = t & 127;
        int h = c >> 2, g = c & 3;
        float v = (g < 3) ? W_iou[(g * 128 + h) * 128 + k] : W_f[h * 128 + k];
        g_Mleaf[t] = __float2half_rn(v);
    }
    if (idx < 896) {
        int h = idx / 7, g = idx - h * 7;
        float v;
        if (g < 3) { int c = g * 128 + h; v = b_iou[c] + b_uiou[c]; }
        else       { int cc = (g - 3) * 128 + h; v = b_wf[h] + b_uf[cc]; }
        g_bias[idx] = v;
    }
    if (idx < 8) g_tbar[idx] = 0;     // reset tail grid barriers each replay
}

__global__ void emb2h_kernel(const float* __restrict__ emb) {
    int stride = gridDim.x * blockDim.x;
    const int total = NN * 128 / 4;
    for (int i = blockIdx.x * blockDim.x + threadIdx.x; i < total; i += stride) {
        float4 v = ((const float4*)emb)[i];
        __half2 p0 = __floats2half2_rn(v.x, v.y);
        __half2 p1 = __floats2half2_rn(v.z, v.w);
        uint2 u;
        u.x = *(const unsigned*)&p0;
        u.y = *(const unsigned*)&p1;
        ((uint2*)g_emb16)[i] = u;
    }
}

__global__ void prep_const_kernel(const float* __restrict__ U_iou, const float* __restrict__ b_iou,
                                  const float* __restrict__ b_uiou, const float* __restrict__ U_f,
                                  const float* __restrict__ b_uf, const float* __restrict__ h0,
                                  const float* __restrict__ b_wf) {
    int w = (blockIdx.x * blockDim.x + threadIdx.x) >> 5;
    int lane = threadIdx.x & 31;
    if (w >= 896) return;
    float s = 0.f;
    if (w < 384) {
        const float* row = U_iou + (size_t)w * 512;
        for (int k = lane; k < 512; k += 32) s += row[k] * h0[k];
    } else {
        const float* row = U_f + (size_t)(w - 384) * 512;
        for (int k = lane; k < 512; k += 32) s += row[k] * h0[k];
    }
#pragma unroll
    for (int o = 16; o; o >>= 1) s += __shfl_xor_sync(0xFFFFFFFFu, s, o);
    if (lane == 0) {
        if (w < 384) {
            int g = w >> 7, h = w & 127;
            g_bleaf[h * 4 + g] = s + b_iou[w] + b_uiou[w];
        } else {
            int cc = w - 384;
            g_cuf[cc] = s + b_uf[cc];
            if (cc < 128) g_bleaf[cc * 4 + 3] = b_wf[cc];
        }
    }
}

// ---------------- persistent fused leaf ----------------
// smem halves: A[2][128][72] 0..18432 ; B[128][136] 18432..35840 ; fp32 consts at byte 71680.
// Epilogue staging reuses A stage 1 (bytes 18432..36864) as Ys[128][36] fp32.
__global__ void __launch_bounds__(256, 2)
leaf_fused(const float* __restrict__ c0,
           float* __restrict__ out_h, float* __restrict__ out_c) {
    extern __shared__ __half smh[];
    uint32_t sbase = (uint32_t)__cvta_generic_to_shared(smh);
    const int BH = 18432;
    float* c0s  = (float*)((char*)smh + 71680);
    float* cufs = c0s + 512;
    float* bls  = cufs + 512;

    int tid = threadIdx.x, wid = tid >> 5, lane = tid & 31;
    int gid = lane >> 2, tig = lane & 3;
    int wr = wid >> 2, wc = wid & 3;
    int colBase = blockIdx.x * 128;
    int hgBase  = blockIdx.x * 32;

    int arow = (lane & 7) + ((lane >> 3) & 1) * 8;
    int ak   = (lane >> 4) * 8;
    int bl   = lane & 15;
    int brow = bl & 7;
    int bk   = ((bl >> 3) & 1) * 8;

#pragma unroll 8
    for (int it = tid; it < 2048; it += 256) {
        int r = it >> 4, q = (it & 15) * 8;
        cp16(sbase + ((BH + r * 136 + q) << 1),
             g_Mleaf + (size_t)(colBase + r) * 128 + q, 16);
    }
    if (tid < 128) {
        cp16((uint32_t)__cvta_generic_to_shared(c0s)  + tid * 16, c0      + tid * 4, 16);
        cp16((uint32_t)__cvta_generic_to_shared(cufs) + tid * 16, g_cuf   + tid * 4, 16);
        cp16((uint32_t)__cvta_generic_to_shared(bls)  + tid * 16, g_bleaf + tid * 4, 16);
    }
    CP_COMMIT();

    auto loadA = [&](int rt, int kc, int st) {
        const __half* src = g_emb16 + (size_t)rt * 128 * 128 + kc * 64;
#pragma unroll
        for (int it = tid; it < 1024; it += 256) {
            int r = it >> 3, q = (it & 7) * 8;
            cp16(sbase + ((st * 9216 + r * 72 + q) << 1), src + (size_t)r * 128 + q, 16);
        }
    };

    loadA(blockIdx.y, 0, 0);
    CP_COMMIT();

    for (int rt = blockIdx.y; rt < 512; rt += 74) {
        loadA(rt, 1, 1);
        CP_COMMIT();

        float acc[4][4][4];
#pragma unroll
        for (int mi = 0; mi < 4; mi++)
#pragma unroll
            for (int ni = 0; ni < 4; ni++)
#pragma unroll
                for (int q = 0; q < 4; q++) acc[mi][ni][q] = 0.f;

#pragma unroll
        for (int kc = 0; kc < 2; kc++) {
            CP_WAIT(1);
            __syncthreads();
#pragma unroll
            for (int ks = 0; ks < 64; ks += 16) {
                uint32_t a[4][4], b[4][2];
#pragma unroll
                for (int mi = 0; mi < 4; mi++)
                    ldm_x4(a[mi], sbase + ((kc * 9216 +
                        (wr * 64 + mi * 16 + arow) * 72 + ks + ak) << 1));
#pragma unroll
                for (int ni = 0; ni < 4; ni++)
                    ldm_x2(b[ni], sbase + ((BH +
                        (wc * 32 + ni * 8 + brow) * 136 + kc * 64 + ks + bk) << 1));
#pragma unroll
                for (int mi = 0; mi < 4; mi++)
#pragma unroll
                    for (int ni = 0; ni < 4; ni++)
                        mma16(acc[mi][ni], a[mi], b[ni]);
            }
            __syncthreads();
            if (kc == 0) {
                int nrt = rt + 74; if (nrt >= 512) nrt = 0;
                loadA(nrt, 0, 0);
                CP_COMMIT();
            }
        }

        // ---- epilogue v2: shuffle gate exchange, 2 staged output passes ----
        float (*Ys)[36] = (float(*)[36])((char*)smh + 18432);
        int rowBaseG = rt * 128;
        int rl0 = wr * 64 + gid + ((tig & 1) << 3);
        int hl0 = wc * 8 + (tig >> 1);
        float cv[4][4];
#pragma unroll
        for (int mi = 0; mi < 4; mi++) {
#pragma unroll
            for (int ni = 0; ni < 4; ni++) {
                int colg = colBase + wc * 32 + ni * 8 + tig * 2;
                float v0 = acc[mi][ni][0] + bls[colg];
                float v1 = acc[mi][ni][1] + bls[colg + 1];
                float v2 = acc[mi][ni][2] + bls[colg];
                float v3 = acc[mi][ni][3] + bls[colg + 1];
                float p0 = __shfl_xor_sync(0xFFFFFFFFu, v0, 1);
                float p1 = __shfl_xor_sync(0xFFFFFFFFu, v1, 1);
                float p2 = __shfl_xor_sync(0xFFFFFFFFu, v2, 1);
                float p3 = __shfl_xor_sync(0xFFFFFFFFu, v3, 1);
                float iv, ov, uv, wf;
                if ((tig & 1) == 0) { iv = v0; ov = v1; uv = p0; wf = p1; }
                else                { iv = p2; ov = p3; uv = v2; wf = v3; }
                int hg = hgBase + wc * 8 + ni * 2 + (tig >> 1);
                float cc = sigf(iv) * tanh_fast(uv);
#pragma unroll
                for (int a = 0; a < 4; a++)
                    cc += sigf(wf + cufs[a * 128 + hg]) * c0s[a * 128 + hg];
                Ys[rl0 + mi * 16][hl0 + ni * 2] = sigf(ov) * tanh_fast(cc);
                cv[mi][ni] = cc;
            }
        }
        __syncthreads();
        {   // write h (+h16), fully coalesced 32B pairs
            int row = tid >> 1, c4 = (tid & 1) * 4;
            size_t ob = (size_t)(rowBaseG + row) * 128 + hgBase;
#pragma unroll
            for (int k = 0; k < 4; k++) {
                float4 v = *(float4*)&Ys[row][c4 + k * 8];
                *(float4*)(out_h + ob + c4 + k * 8) = v;
                __half2 pa = __floats2half2_rn(v.x, v.y);
                __half2 pb = __floats2half2_rn(v.z, v.w);
                uint2 u; u.x = *(const unsigned*)&pa; u.y = *(const unsigned*)&pb;
                *(uint2*)(g_h16 + ob + c4 + k * 8) = u;
            }
        }
        __syncthreads();
#pragma unroll
        for (int mi = 0; mi < 4; mi++)
#pragma unroll
            for (int ni = 0; ni < 4; ni++)
                Ys[rl0 + mi * 16][hl0 + ni * 2] = cv[mi][ni];
        __syncthreads();
        {   // write c
            int row = tid >> 1, c4 = (tid & 1) * 4;
            size_t ob = (size_t)(rowBaseG + row) * 128 + hgBase;
#pragma unroll
            for (int k = 0; k < 4; k++)
                *(float4*)(out_c + ob + c4 + k * 8) = *(float4*)&Ys[row][c4 + k * 8];
        }
        __syncthreads();   // protect Ys (=A stage 1) before next tile's loadA
    }
}

// ---------------- fused inner tile body (shared by fused_inner and tail) ----------------
// smem halves: A[2][128][72] 0..18432 ; B[2][112][72] 18432..34560. Ys reuse pitch 114.
__device__ __forceinline__ void inner_tile_body(
    int embOff, int hOff, int outOff, const float* __restrict__ cprev,
    float* __restrict__ out_h, float* __restrict__ out_c, int n,
    int colTile, int rowTile, __half* smh) {
    uint32_t sbase = (uint32_t)__cvta_generic_to_shared(smh);
    const int BH = 18432;
    const __half* X16  = g_emb16 + (size_t)embOff * 128;
    const __half* Hp16 = g_h16   + (size_t)hOff   * 128;

    int tid = threadIdx.x, wid = tid >> 5, lane = tid & 31;
    int gid = lane >> 2, tig = lane & 3;
    int wr = wid >> 1;
    int wn = wid & 1;
    int rowBase = rowTile * 128, colBase = colTile * 112;

    int arow = (lane & 7) + ((lane >> 3) & 1) * 8;
    int ak   = (lane >> 4) * 8;
    int bl   = lane & 15;
    int brow = bl & 7;
    int bk   = ((bl >> 3) & 1) * 8;

    float acc[2][7][4];
#pragma unroll
    for (int mi = 0; mi < 2; mi++)
#pragma unroll
        for (int nt = 0; nt < 7; nt++)
#pragma unroll
            for (int q = 0; q < 4; q++) acc[mi][nt][q] = 0.f;

    auto loadAB = [&](int kc, int st) {
        int k0 = kc * 64;
        const __half* base; int pitch, koff;
        if (k0 < 128) { base = X16;  pitch = 128; koff = k0; }
        else          { base = Hp16; pitch = 512; koff = k0 - 128; }
        for (int it = tid; it < 1024; it += 256) {
            int r = it >> 3, q = (it & 7) * 8;
            int row = rowBase + r;
            cp16(sbase + ((st * 9216 + r * 72 + q) << 1),
                 base + (size_t)row * pitch + koff + q, (row < n) ? 16u : 0u);
        }
        for (int it = tid; it < 896; it += 256) {
            int r = it >> 3, q = (it & 7) * 8;
            cp16(sbase + ((BH + st * 8064 + r * 72 + q) << 1),
                 g_Mh + (size_t)(colBase + r) * 640 + k0 + q, 16);
        }
    };

    loadAB(0, 0);
    CP_COMMIT();

    for (int kc = 0; kc < 10; kc++) {
        int cur = kc & 1;
        if (kc < 9) {
            loadAB(kc + 1, cur ^ 1);
            CP_COMMIT();
            CP_WAIT(1);
        } else {
            CP_WAIT(0);
        }
        __syncthreads();
#pragma unroll
        for (int ks = 0; ks < 64; ks += 16) {
            uint32_t a[2][4], b[7][2];
#pragma unroll
            for (int mi = 0; mi < 2; mi++)
                ldm_x4(a[mi], sbase + ((cur * 9216 +
                    (wr * 32 + mi * 16 + arow) * 72 + ks + ak) << 1));
#pragma unroll
            for (int nt = 0; nt < 7; nt++)
                ldm_x2(b[nt], sbase + ((BH + cur * 8064 +
                    (wn * 56 + nt * 8 + brow) * 72 + ks + bk) << 1));
#pragma unroll
            for (int mi = 0; mi < 2; mi++)
#pragma unroll
                for (int nt = 0; nt < 7; nt++)
                    mma16(acc[mi][nt], a[mi], b[nt]);
        }
        __syncthreads();
    }

    float (*Ys)[114] = (float(*)[114])smh;
#pragma unroll
    for (int mi = 0; mi < 2; mi++) {
        int r0 = wr * 32 + mi * 16 + gid;
#pragma unroll
        for (int nt = 0; nt < 7; nt++) {
            int col = wn * 56 + nt * 8 + tig * 2;
            float bx = g_bias[colBase + col], by = g_bias[colBase + col + 1];
            *(float2*)&Ys[r0][col]     = make_float2(acc[mi][nt][0] + bx, acc[mi][nt][1] + by);
            *(float2*)&Ys[r0 + 8][col] = make_float2(acc[mi][nt][2] + bx, acc[mi][nt][3] + by);
        }
    }
    __syncthreads();

    int row = tid >> 1, hhalf = tid & 1;
    int J = rowBase + row;
    if (J < n) {
        int hg0 = colTile * 16 + hhalf * 8;
        float4 cpv[4][2];
#pragma unroll
        for (int a = 0; a < 4; a++) {
            const float* cp = cprev + (size_t)(4 * J + a) * 128 + hg0;
            cpv[a][0] = *(const float4*)cp;
            cpv[a][1] = *(const float4*)(cp + 4);
        }
        float hb[8], cb[8];
#pragma unroll
        for (int j = 0; j < 8; j++) {
            const float* g = &Ys[row][(hhalf * 8 + j) * 7];
            float cc = sigf(g[0]) * tanh_fast(g[2]);
#pragma unroll
            for (int a = 0; a < 4; a++)
                cc += sigf(g[3 + a]) * ((const float*)&cpv[a][j >> 2])[j & 3];
            hb[j] = sigf(g[1]) * tanh_fast(cc);
            cb[j] = cc;
        }
        size_t ob = (size_t)(outOff + J) * 128 + hg0;
        *(float4*)(out_h + ob)     = make_float4(hb[0], hb[1], hb[2], hb[3]);
        *(float4*)(out_h + ob + 4) = make_float4(hb[4], hb[5], hb[6], hb[7]);
        *(float4*)(out_c + ob)     = make_float4(cb[0], cb[1], cb[2], cb[3]);
        *(float4*)(out_c + ob + 4) = make_float4(cb[4], cb[5], cb[6], cb[7]);
        __half2 p0 = __floats2half2_rn(hb[0], hb[1]);
        __half2 p1 = __floats2half2_rn(hb[2], hb[3]);
        __half2 p2 = __floats2half2_rn(hb[4], hb[5]);
        __half2 p3 = __floats2half2_rn(hb[6], hb[7]);
        uint4 u;
        u.x = *(const unsigned*)&p0; u.y = *(const unsigned*)&p1;
        u.z = *(const unsigned*)&p2; u.w = *(const unsigned*)&p3;
        *(uint4*)(g_h16 + ob) = u;
    }
    __syncthreads();   // Ys (=A/B staging) must be fully read before reuse
}

__global__ void __launch_bounds__(256, 2)
fused_inner(int embOff, int hOff, int outOff, const float* __restrict__ cprev,
            float* __restrict__ out_h, float* __restrict__ out_c, int n) {
    extern __shared__ __half smh[];
    inner_tile_body(embOff, hOff, outOff, cprev, out_h, out_c, n,
                    blockIdx.x, blockIdx.y, smh);
}

// ---------------- persistent tail: levels n=1024,256,64,16,4,1 with grid barriers ----
__global__ void __launch_bounds__(256, 2)
tail_fused(float* __restrict__ out_h, float* __restrict__ out_c) {
    extern __shared__ __half smh[];
    const int ln[6] = {1024, 256, 64, 16, 4, 1};
    const int eo[6] = {86016, 87040, 87296, 87360, 87376, 87380};
    const int ho[6] = {81920, 86016, 87040, 87296, 87360, 87376};
    int ct = blockIdx.x & 7, rt2 = blockIdx.x >> 3;

#pragma unroll 1
    for (int l = 0; l < 6; l++) {
        if (rt2 * 128 < ln[l])
            inner_tile_body(eo[l], ho[l], eo[l], out_c + (size_t)ho[l] * 128,
                            out_h, out_c, ln[l], ct, rt2, smh);
        // grid barrier l
        __threadfence();
        __syncthreads();
        if (threadIdx.x == 0) {
            atomicAdd(&g_tbar[l], 1);
            while (((volatile int*)g_tbar)[l] < 64) {}
        }
        __syncthreads();
        __threadfence();
    }
}

// ---------------- launch ----------------
extern "C" void kernel_launch(void* const* d_in, const int* in_sizes, int n_in,
                              void* d_out, int out_size) {
    const float* emb    = (const float*)d_in[0];
    const float* W_iou  = (const float*)d_in[1];
    const float* b_iou  = (const float*)d_in[2];
    const float* U_iou  = (const float*)d_in[3];
    const float* b_uiou = (const float*)d_in[4];
    const float* W_f    = (const float*)d_in[5];
    const float* b_wf   = (const float*)d_in[6];
    const float* U_f    = (const float*)d_in[7];
    const float* b_uf   = (const float*)d_in[8];
    const float* h0     = (const float*)d_in[9];
    const float* c0     = (const float*)d_in[10];

    float* out_h = (float*)d_out;
    float* out_c = out_h + (size_t)NN * 128;

    cudaFuncSetAttribute(leaf_fused,  cudaFuncAttributeMaxDynamicSharedMemorySize, 77824);
    cudaFuncSetAttribute(fused_inner, cudaFuncAttributeMaxDynamicSharedMemorySize, 69120);
    cudaFuncSetAttribute(tail_fused,  cudaFuncAttributeMaxDynamicSharedMemorySize, 69120);

    prep_M_kernel<<<512, 256>>>(W_iou, U_iou, b_iou, b_uiou, W_f, U_f, b_wf, b_uf);
    emb2h_kernel<<<512, 256>>>(emb);
    prep_const_kernel<<<112, 256>>>(U_iou, b_iou, b_uiou, U_f, b_uf, h0, b_wf);

    const int offs1 = 65536, offs2 = 81920;   // level offsets for n=16384, 4096

    // leaf level: persistent fused kernel (also fills g_h16[0:65536])
    leaf_fused<<<dim3(4, 74), 256, 77824>>>(c0, out_h, out_c);

    // level n=16384
    fused_inner<<<dim3(8, 128), 256, 69120>>>(
        offs1, 0, offs1, out_c, out_h, out_c, 16384);
    // level n=4096
    fused_inner<<<dim3(8, 32), 256, 69120>>>(
        offs2, offs1, offs2, out_c + (size_t)offs1 * 128, out_h, out_c, 4096);

    // levels n=1024..1: one persistent kernel, 64 CTAs, grid barriers
    tail_fused<<<64, 256, 69120>>>(out_h, out_c);
}

// round 16
// speedup vs baseline: 1.5352x; 1.5352x over previous
#include <cuda_runtime.h>
#include <cuda_fp16.h>
#include <math.h>
#include <stdint.h>

// Tree-LSTM, 4-ary, depth 8. E=H=128, A=4. N_NODES=87381, leaves=65536.
// R16: revert to R14 structure (R15's shuffle epilogue + persistent tail both
// regressed: register spills). Single change vs R14: B-operand ldmatrix.x2 pairs
// fused into .x4 (leaf 4->2, inner 7->3x4+1x2 per ks-step).

#define NN     87381
#define NLEAF  65536

__device__ __half g_Mh[896 * 640];             // inner weight, PERMUTED cp = h*7+g
__device__ float  g_bias[896];                 // inner bias, PERMUTED
__device__ __half g_Mleaf[512 * 128];          // leaf weight, PERMUTED col = h*4+gate
__device__ float  g_bleaf[512];                // leaf bias, PERMUTED
__device__ float  g_cuf[512];
__device__ __half g_emb16[(size_t)NN * 128];
__device__ __half g_h16[(size_t)NN * 128];

__device__ __forceinline__ float sigf(float x) {
    return __fdividef(1.f, 1.f + __expf(-x));
}
__device__ __forceinline__ float tanh_fast(float x) {
    return 1.f - __fdividef(2.f, __expf(2.f * x) + 1.f);
}
__device__ __forceinline__ void cp16(uint32_t dst, const void* src, uint32_t srcsz) {
    asm volatile("cp.async.ca.shared.global [%0], [%1], 16, %2;"
                 :: "r"(dst), "l"(src), "r"(srcsz));
}
#define CP_COMMIT() asm volatile("cp.async.commit_group;" ::: "memory")
#define CP_WAIT(N)  asm volatile("cp.async.wait_group %0;" :: "n"(N) : "memory")

__device__ __forceinline__ void ldm_x4(uint32_t* r, uint32_t addr) {
    asm volatile("ldmatrix.sync.aligned.m8n8.x4.shared.b16 {%0,%1,%2,%3}, [%4];"
                 : "=r"(r[0]), "=r"(r[1]), "=r"(r[2]), "=r"(r[3]) : "r"(addr));
}
__device__ __forceinline__ void ldm_x4v(uint32_t& r0, uint32_t& r1, uint32_t& r2,
                                        uint32_t& r3, uint32_t addr) {
    asm volatile("ldmatrix.sync.aligned.m8n8.x4.shared.b16 {%0,%1,%2,%3}, [%4];"
                 : "=r"(r0), "=r"(r1), "=r"(r2), "=r"(r3) : "r"(addr));
}
__device__ __forceinline__ void ldm_x2(uint32_t* r, uint32_t addr) {
    asm volatile("ldmatrix.sync.aligned.m8n8.x2.shared.b16 {%0,%1}, [%2];"
                 : "=r"(r[0]), "=r"(r[1]) : "r"(addr));
}
__device__ __forceinline__ void mma16(float* c, const uint32_t* a, const uint32_t* b) {
    asm volatile(
        "mma.sync.aligned.m16n8k16.row.col.f32.f16.f16.f32 "
        "{%0,%1,%2,%3}, {%4,%5,%6,%7}, {%8,%9}, {%0,%1,%2,%3};"
        : "+f"(c[0]), "+f"(c[1]), "+f"(c[2]), "+f"(c[3])
        : "r"(a[0]), "r"(a[1]), "r"(a[2]), "r"(a[3]), "r"(b[0]), "r"(b[1]));
}

// ---------------- prep ----------------
__global__ void prep_M_kernel(const float* __restrict__ W_iou, const float* __restrict__ U_iou,
                              const float* __restrict__ b_iou, const float* __restrict__ b_uiou,
                              const float* __restrict__ W_f,  const float* __restrict__ U_f,
                              const float* __restrict__ b_wf, const float* __restrict__ b_uf) {
    int stride = gridDim.x * blockDim.x;
    int idx = blockIdx.x * blockDim.x + threadIdx.x;
    for (int t = idx; t < 896 * 640; t += stride) {
        int cp = t / 640, k = t - cp * 640;
        int h = cp / 7, g = cp - h * 7;
        float v;
        if (g < 3) {
            int c = g * 128 + h;
            v = (k < 128) ? W_iou[c * 128 + k] : U_iou[c * 512 + (k - 128)];
        } else {
            int cc = (g - 3) * 128 + h;
            v = (k < 128) ? W_f[h * 128 + k] : U_f[cc * 512 + (k - 128)];
        }
        g_Mh[t] = __float2half_rn(v);
    }
    for (int t = idx; t < 512 * 128; t += stride) {
        int c = t >> 7, k = t & 127;
        int h = c >> 2, g = c & 3;
        float v = (g < 3) ? W_iou[(g * 128 + h) * 128 + k] : W_f[h * 128 + k];
        g_Mleaf[t] = __float2half_rn(v);
    }
    if (idx < 896) {
        int h = idx / 7, g = idx - h * 7;
        float v;
        if (g < 3) { int c = g * 128 + h; v = b_iou[c] + b_uiou[c]; }
        else       { int cc = (g - 3) * 128 + h; v = b_wf[h] + b_uf[cc]; }
        g_bias[idx] = v;
    }
}

__global__ void emb2h_kernel(const float* __restrict__ emb) {
    int stride = gridDim.x * blockDim.x;
    const int total = NN * 128 / 4;
    for (int i = blockIdx.x * blockDim.x + threadIdx.x; i < total; i += stride) {
        float4 v = ((const float4*)emb)[i];
        __half2 p0 = __floats2half2_rn(v.x, v.y);
        __half2 p1 = __floats2half2_rn(v.z, v.w);
        uint2 u;
        u.x = *(const unsigned*)&p0;
        u.y = *(const unsigned*)&p1;
        ((uint2*)g_emb16)[i] = u;
    }
}

// one warp per output row: lane-strided loads + shfl reduction
__global__ void prep_const_kernel(const float* __restrict__ U_iou, const float* __restrict__ b_iou,
                                  const float* __restrict__ b_uiou, const float* __restrict__ U_f,
                                  const float* __restrict__ b_uf, const float* __restrict__ h0,
                                  const float* __restrict__ b_wf) {
    int w = (blockIdx.x * blockDim.x + threadIdx.x) >> 5;
    int lane = threadIdx.x & 31;
    if (w >= 896) return;
    float s = 0.f;
    if (w < 384) {
        const float* row = U_iou + (size_t)w * 512;
        for (int k = lane; k < 512; k += 32) s += row[k] * h0[k];
    } else {
        const float* row = U_f + (size_t)(w - 384) * 512;
        for (int k = lane; k < 512; k += 32) s += row[k] * h0[k];
    }
#pragma unroll
    for (int o = 16; o; o >>= 1) s += __shfl_xor_sync(0xFFFFFFFFu, s, o);
    if (lane == 0) {
        if (w < 384) {
            int g = w >> 7, h = w & 127;
            g_bleaf[h * 4 + g] = s + b_iou[w] + b_uiou[w];
        } else {
            int cc = w - 384;
            g_cuf[cc] = s + b_uf[cc];
            if (cc < 128) g_bleaf[cc * 4 + 3] = b_wf[cc];
        }
    }
}

// ---------------- persistent fused leaf (R14 epilogue; B loads via ldm_x4) ----------------
// smem halves: A[2][128][72] 0..18432 ; B[128][136] 18432..35840 ; fp32 consts at byte 71680.
__global__ void __launch_bounds__(256, 2)
leaf_fused(const float* __restrict__ c0,
           float* __restrict__ out_h, float* __restrict__ out_c) {
    extern __shared__ __half smh[];
    uint32_t sbase = (uint32_t)__cvta_generic_to_shared(smh);
    const int BH = 18432;
    float* c0s  = (float*)((char*)smh + 71680);
    float* cufs = c0s + 512;
    float* bls  = cufs + 512;

    int tid = threadIdx.x, wid = tid >> 5, lane = tid & 31;
    int gid = lane >> 2, tig = lane & 3;
    int wr = wid >> 2, wc = wid & 3;
    int colBase = blockIdx.x * 128;
    int hgBase  = blockIdx.x * 32;

    int arow = (lane & 7) + ((lane >> 3) & 1) * 8;
    int ak   = (lane >> 4) * 8;
    int mrow = lane & 7;          // x4 B addressing: matrix = lane>>3
    int mq   = lane >> 3;         // 0..3

#pragma unroll 8
    for (int it = tid; it < 2048; it += 256) {
        int r = it >> 4, q = (it & 15) * 8;
        cp16(sbase + ((BH + r * 136 + q) << 1),
             g_Mleaf + (size_t)(colBase + r) * 128 + q, 16);
    }
    if (tid < 128) {
        cp16((uint32_t)__cvta_generic_to_shared(c0s)  + tid * 16, c0      + tid * 4, 16);
        cp16((uint32_t)__cvta_generic_to_shared(cufs) + tid * 16, g_cuf   + tid * 4, 16);
        cp16((uint32_t)__cvta_generic_to_shared(bls)  + tid * 16, g_bleaf + tid * 4, 16);
    }
    CP_COMMIT();

    auto loadA = [&](int rt, int kc, int st) {
        const __half* src = g_emb16 + (size_t)rt * 128 * 128 + kc * 64;
#pragma unroll
        for (int it = tid; it < 1024; it += 256) {
            int r = it >> 3, q = (it & 7) * 8;
            cp16(sbase + ((st * 9216 + r * 72 + q) << 1), src + (size_t)r * 128 + q, 16);
        }
    };

    loadA(blockIdx.y, 0, 0);
    CP_COMMIT();

    for (int rt = blockIdx.y; rt < 512; rt += 74) {
        loadA(rt, 1, 1);
        CP_COMMIT();

        float acc[4][4][4];
#pragma unroll
        for (int mi = 0; mi < 4; mi++)
#pragma unroll
            for (int ni = 0; ni < 4; ni++)
#pragma unroll
                for (int q = 0; q < 4; q++) acc[mi][ni][q] = 0.f;

#pragma unroll
        for (int kc = 0; kc < 2; kc++) {
            CP_WAIT(1);
            __syncthreads();
#pragma unroll
            for (int ks = 0; ks < 64; ks += 16) {
                uint32_t a[4][4], b[4][2];
#pragma unroll
                for (int mi = 0; mi < 4; mi++)
                    ldm_x4(a[mi], sbase + ((kc * 9216 +
                        (wr * 64 + mi * 16 + arow) * 72 + ks + ak) << 1));
                // B: two x4 loads cover all 4 n-tiles (mat = lane>>3:
                //   mat0 = ni+0 k-lo, mat1 = ni+0 k-hi, mat2 = ni+1 k-lo, mat3 = ni+1 k-hi)
#pragma unroll
                for (int nip = 0; nip < 4; nip += 2)
                    ldm_x4v(b[nip][0], b[nip][1], b[nip + 1][0], b[nip + 1][1],
                            sbase + ((BH +
                        (wc * 32 + (nip + (mq >> 1)) * 8 + mrow) * 136 +
                        kc * 64 + ks + (mq & 1) * 8) << 1));
#pragma unroll
                for (int mi = 0; mi < 4; mi++)
#pragma unroll
                    for (int ni = 0; ni < 4; ni++)
                        mma16(acc[mi][ni], a[mi], b[ni]);
            }
            __syncthreads();
            if (kc == 0) {
                int nrt = rt + 74; if (nrt >= 512) nrt = 0;
                loadA(nrt, 0, 0);
                CP_COMMIT();
            }
        }

        // R14 epilogue: 4 column quarters through A stage 1 (128x36 fp32)
        float (*Ysq)[36] = (float(*)[36])((char*)smh + 18432);
        int rowBaseG = rt * 128;
        int row = tid >> 1, hq = (tid & 1) * 4;
#pragma unroll
        for (int wq = 0; wq < 4; wq++) {
            if (wc == wq) {
#pragma unroll
                for (int mi = 0; mi < 4; mi++) {
                    int r0 = wr * 64 + mi * 16 + gid;
#pragma unroll
                    for (int ni = 0; ni < 4; ni++) {
                        int col = ni * 8 + tig * 2;
                        float bx = bls[colBase + wq * 32 + col];
                        float by = bls[colBase + wq * 32 + col + 1];
                        Ysq[r0][col]         = acc[mi][ni][0] + bx;
                        Ysq[r0][col + 1]     = acc[mi][ni][1] + by;
                        Ysq[r0 + 8][col]     = acc[mi][ni][2] + bx;
                        Ysq[r0 + 8][col + 1] = acc[mi][ni][3] + by;
                    }
                }
            }
            __syncthreads();
            float hb[4], cb[4];
#pragma unroll
            for (int j = 0; j < 4; j++) {
                int hl = hq + j;
                float4 v = *(const float4*)&Ysq[row][hl * 4];   // i, o, u, wf
                int hg = hgBase + wq * 8 + hl;
                float cc = sigf(v.x) * tanh_fast(v.z);
#pragma unroll
                for (int a = 0; a < 4; a++)
                    cc += sigf(v.w + cufs[a * 128 + hg]) * c0s[a * 128 + hg];
                hb[j] = sigf(v.y) * tanh_fast(cc);
                cb[j] = cc;
            }
            size_t ob = (size_t)(rowBaseG + row) * 128 + hgBase + wq * 8 + hq;
            *(float4*)(out_h + ob) = make_float4(hb[0], hb[1], hb[2], hb[3]);
            *(float4*)(out_c + ob) = make_float4(cb[0], cb[1], cb[2], cb[3]);
            __half2 p0 = __floats2half2_rn(hb[0], hb[1]);
            __half2 p1 = __floats2half2_rn(hb[2], hb[3]);
            uint2 u; u.x = *(const unsigned*)&p0; u.y = *(const unsigned*)&p1;
            *(uint2*)(g_h16 + ob) = u;
            __syncthreads();
        }
    }
}

// ---------------- fused inner: GEMM (128 x 112, K=640) + gates ----------------
// smem halves: A[2][128][72] 0..18432 ; B[2][112][72] 18432..34560.
// Ys reuse pitch 114. grid (8, ceil(n/128)). Warp tile 32 rows x 56 cols.
__global__ void __launch_bounds__(256, 2)
fused_inner(int embOff, int hOff, int outOff, const float* __restrict__ cprev,
            float* __restrict__ out_h, float* __restrict__ out_c, int n) {
    extern __shared__ __half smh[];
    uint32_t sbase = (uint32_t)__cvta_generic_to_shared(smh);
    const int BH = 18432;
    const __half* X16  = g_emb16 + (size_t)embOff * 128;
    const __half* Hp16 = g_h16   + (size_t)hOff   * 128;

    int tid = threadIdx.x, wid = tid >> 5, lane = tid & 31;
    int gid = lane >> 2, tig = lane & 3;
    int wr = wid >> 1;
    int wn = wid & 1;
    int rowBase = blockIdx.y * 128, colBase = blockIdx.x * 112;

    int arow = (lane & 7) + ((lane >> 3) & 1) * 8;
    int ak   = (lane >> 4) * 8;
    int bl   = lane & 15;
    int brow = bl & 7;
    int bk   = ((bl >> 3) & 1) * 8;
    int mrow = lane & 7;
    int mq   = lane >> 3;

    float acc[2][7][4];
#pragma unroll
    for (int mi = 0; mi < 2; mi++)
#pragma unroll
        for (int nt = 0; nt < 7; nt++)
#pragma unroll
            for (int q = 0; q < 4; q++) acc[mi][nt][q] = 0.f;

    auto loadAB = [&](int kc, int st) {
        int k0 = kc * 64;
        const __half* base; int pitch, koff;
        if (k0 < 128) { base = X16;  pitch = 128; koff = k0; }
        else          { base = Hp16; pitch = 512; koff = k0 - 128; }
        for (int it = tid; it < 1024; it += 256) {
            int r = it >> 3, q = (it & 7) * 8;
            int row = rowBase + r;
            cp16(sbase + ((st * 9216 + r * 72 + q) << 1),
                 base + (size_t)row * pitch + koff + q, (row < n) ? 16u : 0u);
        }
        for (int it = tid; it < 896; it += 256) {
            int r = it >> 3, q = (it & 7) * 8;
            cp16(sbase + ((BH + st * 8064 + r * 72 + q) << 1),
                 g_Mh + (size_t)(colBase + r) * 640 + k0 + q, 16);
        }
    };

    loadAB(0, 0);
    CP_COMMIT();

    for (int kc = 0; kc < 10; kc++) {
        int cur = kc & 1;
        if (kc < 9) {
            loadAB(kc + 1, cur ^ 1);
            CP_COMMIT();
            CP_WAIT(1);
        } else {
            CP_WAIT(0);
        }
        __syncthreads();
#pragma unroll
        for (int ks = 0; ks < 64; ks += 16) {
            uint32_t a[2][4], b[7][2];
#pragma unroll
            for (int mi = 0; mi < 2; mi++)
                ldm_x4(a[mi], sbase + ((cur * 9216 +
                    (wr * 32 + mi * 16 + arow) * 72 + ks + ak) << 1));
            // B: 3 x4 loads cover n-tiles 0..5, one x2 for tile 6
#pragma unroll
            for (int nip = 0; nip < 6; nip += 2)
                ldm_x4v(b[nip][0], b[nip][1], b[nip + 1][0], b[nip + 1][1],
                        sbase + ((BH + cur * 8064 +
                    (wn * 56 + (nip + (mq >> 1)) * 8 + mrow) * 72 +
                    ks + (mq & 1) * 8) << 1));
            ldm_x2(b[6], sbase + ((BH + cur * 8064 +
                (wn * 56 + 6 * 8 + brow) * 72 + ks + bk) << 1));
#pragma unroll
            for (int mi = 0; mi < 2; mi++)
#pragma unroll
                for (int nt = 0; nt < 7; nt++)
                    mma16(acc[mi][nt], a[mi], b[nt]);
        }
        __syncthreads();
    }

    // spill full Y tile (+bias) into reused smem, pitch 114 floats
    float (*Ys)[114] = (float(*)[114])smh;
#pragma unroll
    for (int mi = 0; mi < 2; mi++) {
        int r0 = wr * 32 + mi * 16 + gid;
#pragma unroll
        for (int nt = 0; nt < 7; nt++) {
            int col = wn * 56 + nt * 8 + tig * 2;
            float bx = g_bias[colBase + col], by = g_bias[colBase + col + 1];
            *(float2*)&Ys[r0][col]     = make_float2(acc[mi][nt][0] + bx, acc[mi][nt][1] + by);
            *(float2*)&Ys[r0 + 8][col] = make_float2(acc[mi][nt][2] + bx, acc[mi][nt][3] + by);
        }
    }
    __syncthreads();

    // gates: thread -> (row = tid>>1, 8 consecutive H)
    int row = tid >> 1, hhalf = tid & 1;
    int J = rowBase + row;
    if (J < n) {
        int hg0 = blockIdx.x * 16 + hhalf * 8;
        float4 cpv[4][2];
#pragma unroll
        for (int a = 0; a < 4; a++) {
            const float* cp = cprev + (size_t)(4 * J + a) * 128 + hg0;
            cpv[a][0] = *(const float4*)cp;
            cpv[a][1] = *(const float4*)(cp + 4);
        }
        float hb[8], cb[8];
#pragma unroll
        for (int j = 0; j < 8; j++) {
            const float* g = &Ys[row][(hhalf * 8 + j) * 7];
            float cc = sigf(g[0]) * tanh_fast(g[2]);
#pragma unroll
            for (int a = 0; a < 4; a++)
                cc += sigf(g[3 + a]) * ((const float*)&cpv[a][j >> 2])[j & 3];
            hb[j] = sigf(g[1]) * tanh_fast(cc);
            cb[j] = cc;
        }
        size_t ob = (size_t)(outOff + J) * 128 + hg0;
        *(float4*)(out_h + ob)     = make_float4(hb[0], hb[1], hb[2], hb[3]);
        *(float4*)(out_h + ob + 4) = make_float4(hb[4], hb[5], hb[6], hb[7]);
        *(float4*)(out_c + ob)     = make_float4(cb[0], cb[1], cb[2], cb[3]);
        *(float4*)(out_c + ob + 4) = make_float4(cb[4], cb[5], cb[6], cb[7]);
        __half2 p0 = __floats2half2_rn(hb[0], hb[1]);
        __half2 p1 = __floats2half2_rn(hb[2], hb[3]);
        __half2 p2 = __floats2half2_rn(hb[4], hb[5]);
        __half2 p3 = __floats2half2_rn(hb[6], hb[7]);
        uint4 u;
        u.x = *(const unsigned*)&p0; u.y = *(const unsigned*)&p1;
        u.z = *(const unsigned*)&p2; u.w = *(const unsigned*)&p3;
        *(uint4*)(g_h16 + ob) = u;
    }
}

// ---------------- launch ----------------
extern "C" void kernel_launch(void* const* d_in, const int* in_sizes, int n_in,
                              void* d_out, int out_size) {
    const float* emb    = (const float*)d_in[0];
    const float* W_iou  = (const float*)d_in[1];
    const float* b_iou  = (const float*)d_in[2];
    const float* U_iou  = (const float*)d_in[3];
    const float* b_uiou = (const float*)d_in[4];
    const float* W_f    = (const float*)d_in[5];
    const float* b_wf   = (const float*)d_in[6];
    const float* U_f    = (const float*)d_in[7];
    const float* b_uf   = (const float*)d_in[8];
    const float* h0     = (const float*)d_in[9];
    const float* c0     = (const float*)d_in[10];

    float* out_h = (float*)d_out;
    float* out_c = out_h + (size_t)NN * 128;

    cudaFuncSetAttribute(leaf_fused,  cudaFuncAttributeMaxDynamicSharedMemorySize, 77824);
    cudaFuncSetAttribute(fused_inner, cudaFuncAttributeMaxDynamicSharedMemorySize, 69120);

    prep_M_kernel<<<512, 256>>>(W_iou, U_iou, b_iou, b_uiou, W_f, U_f, b_wf, b_uf);
    emb2h_kernel<<<512, 256>>>(emb);
    prep_const_kernel<<<112, 256>>>(U_iou, b_iou, b_uiou, U_f, b_uf, h0, b_wf);

    const int lev_n[9] = {65536, 16384, 4096, 1024, 256, 64, 16, 4, 1};
    int offs[10];
    offs[0] = 0;
    for (int i = 0; i < 9; i++) offs[i + 1] = offs[i] + lev_n[i];

    // leaf level: persistent fused kernel (also fills g_h16[0:65536])
    leaf_fused<<<dim3(4, 74), 256, 77824>>>(c0, out_h, out_c);

    // inner levels 7..0: fused GEMM+gates
    for (int i = 1; i < 9; i++) {
        int n = lev_n[i];
        const float* Cp = out_c + (size_t)offs[i - 1] * 128;
        fused_inner<<<dim3(8, (n + 127) / 128), 256, 69120>>>(
            offs[i], offs[i - 1], offs[i], Cp, out_h, out_c, n);
    }
}

// round 17
// speedup vs baseline: 1.5885x; 1.0347x over previous
#include <cuda_runtime.h>
#include <cuda_fp16.h>
#include <math.h>
#include <stdint.h>

// Tree-LSTM, 4-ary, depth 8. E=H=128, A=4. N_NODES=87381, leaves=65536.
// R17: R16 + MUFU.TANH gate math (tanh.approx.f32): 8 MUFU per (node,h)
// instead of 16. Everything else identical to R16 (273.5us).

#define NN     87381
#define NLEAF  65536

__device__ __half g_Mh[896 * 640];             // inner weight, PERMUTED cp = h*7+g
__device__ float  g_bias[896];                 // inner bias, PERMUTED
__device__ __half g_Mleaf[512 * 128];          // leaf weight, PERMUTED col = h*4+gate
__device__ float  g_bleaf[512];                // leaf bias, PERMUTED
__device__ float  g_cuf[512];
__device__ __half g_emb16[(size_t)NN * 128];
__device__ __half g_h16[(size_t)NN * 128];

__device__ __forceinline__ float tanh_fast(float x) {
    float r; asm("tanh.approx.f32 %0, %1;" : "=f"(r) : "f"(x)); return r;
}
__device__ __forceinline__ float sigf(float x) {
    float r; asm("tanh.approx.f32 %0, %1;" : "=f"(r) : "f"(0.5f * x));
    return fmaf(r, 0.5f, 0.5f);
}
__device__ __forceinline__ void cp16(uint32_t dst, const void* src, uint32_t srcsz) {
    asm volatile("cp.async.ca.shared.global [%0], [%1], 16, %2;"
                 :: "r"(dst), "l"(src), "r"(srcsz));
}
#define CP_COMMIT() asm volatile("cp.async.commit_group;" ::: "memory")
#define CP_WAIT(N)  asm volatile("cp.async.wait_group %0;" :: "n"(N) : "memory")

__device__ __forceinline__ void ldm_x4(uint32_t* r, uint32_t addr) {
    asm volatile("ldmatrix.sync.aligned.m8n8.x4.shared.b16 {%0,%1,%2,%3}, [%4];"
                 : "=r"(r[0]), "=r"(r[1]), "=r"(r[2]), "=r"(r[3]) : "r"(addr));
}
__device__ __forceinline__ void ldm_x4v(uint32_t& r0, uint32_t& r1, uint32_t& r2,
                                        uint32_t& r3, uint32_t addr) {
    asm volatile("ldmatrix.sync.aligned.m8n8.x4.shared.b16 {%0,%1,%2,%3}, [%4];"
                 : "=r"(r0), "=r"(r1), "=r"(r2), "=r"(r3) : "r"(addr));
}
__device__ __forceinline__ void ldm_x2(uint32_t* r, uint32_t addr) {
    asm volatile("ldmatrix.sync.aligned.m8n8.x2.shared.b16 {%0,%1}, [%2];"
                 : "=r"(r[0]), "=r"(r[1]) : "r"(addr));
}
__device__ __forceinline__ void mma16(float* c, const uint32_t* a, const uint32_t* b) {
    asm volatile(
        "mma.sync.aligned.m16n8k16.row.col.f32.f16.f16.f32 "
        "{%0,%1,%2,%3}, {%4,%5,%6,%7}, {%8,%9}, {%0,%1,%2,%3};"
        : "+f"(c[0]), "+f"(c[1]), "+f"(c[2]), "+f"(c[3])
        : "r"(a[0]), "r"(a[1]), "r"(a[2]), "r"(a[3]), "r"(b[0]), "r"(b[1]));
}

// ---------------- prep ----------------
__global__ void prep_M_kernel(const float* __restrict__ W_iou, const float* __restrict__ U_iou,
                              const float* __restrict__ b_iou, const float* __restrict__ b_uiou,
                              const float* __restrict__ W_f,  const float* __restrict__ U_f,
                              const float* __restrict__ b_wf, const float* __restrict__ b_uf) {
    int stride = gridDim.x * blockDim.x;
    int idx = blockIdx.x * blockDim.x + threadIdx.x;
    for (int t = idx; t < 896 * 640; t += stride) {
        int cp = t / 640, k = t - cp * 640;
        int h = cp / 7, g = cp - h * 7;
        float v;
        if (g < 3) {
            int c = g * 128 + h;
            v = (k < 128) ? W_iou[c * 128 + k] : U_iou[c * 512 + (k - 128)];
        } else {
            int cc = (g - 3) * 128 + h;
            v = (k < 128) ? W_f[h * 128 + k] : U_f[cc * 512 + (k - 128)];
        }
        g_Mh[t] = __float2half_rn(v);
    }
    for (int t = idx; t < 512 * 128; t += stride) {
        int c = t >> 7, k = t & 127;
        int h = c >> 2, g = c & 3;
        float v = (g < 3) ? W_iou[(g * 128 + h) * 128 + k] : W_f[h * 128 + k];
        g_Mleaf[t] = __float2half_rn(v);
    }
    if (idx < 896) {
        int h = idx / 7, g = idx - h * 7;
        float v;
        if (g < 3) { int c = g * 128 + h; v = b_iou[c] + b_uiou[c]; }
        else       { int cc = (g - 3) * 128 + h; v = b_wf[h] + b_uf[cc]; }
        g_bias[idx] = v;
    }
}

__global__ void emb2h_kernel(const float* __restrict__ emb) {
    int stride = gridDim.x * blockDim.x;
    const int total = NN * 128 / 4;
    for (int i = blockIdx.x * blockDim.x + threadIdx.x; i < total; i += stride) {
        float4 v = ((const float4*)emb)[i];
        __half2 p0 = __floats2half2_rn(v.x, v.y);
        __half2 p1 = __floats2half2_rn(v.z, v.w);
        uint2 u;
        u.x = *(const unsigned*)&p0;
        u.y = *(const unsigned*)&p1;
        ((uint2*)g_emb16)[i] = u;
    }
}

// one warp per output row: lane-strided loads + shfl reduction
__global__ void prep_const_kernel(const float* __restrict__ U_iou, const float* __restrict__ b_iou,
                                  const float* __restrict__ b_uiou, const float* __restrict__ U_f,
                                  const float* __restrict__ b_uf, const float* __restrict__ h0,
                                  const float* __restrict__ b_wf) {
    int w = (blockIdx.x * blockDim.x + threadIdx.x) >> 5;
    int lane = threadIdx.x & 31;
    if (w >= 896) return;
    float s = 0.f;
    if (w < 384) {
        const float* row = U_iou + (size_t)w * 512;
        for (int k = lane; k < 512; k += 32) s += row[k] * h0[k];
    } else {
        const float* row = U_f + (size_t)(w - 384) * 512;
        for (int k = lane; k < 512; k += 32) s += row[k] * h0[k];
    }
#pragma unroll
    for (int o = 16; o; o >>= 1) s += __shfl_xor_sync(0xFFFFFFFFu, s, o);
    if (lane == 0) {
        if (w < 384) {
            int g = w >> 7, h = w & 127;
            g_bleaf[h * 4 + g] = s + b_iou[w] + b_uiou[w];
        } else {
            int cc = w - 384;
            g_cuf[cc] = s + b_uf[cc];
            if (cc < 128) g_bleaf[cc * 4 + 3] = b_wf[cc];
        }
    }
}

// ---------------- persistent fused leaf ----------------
// smem halves: A[2][128][72] 0..18432 ; B[128][136] 18432..35840 ; fp32 consts at byte 71680.
__global__ void __launch_bounds__(256, 2)
leaf_fused(const float* __restrict__ c0,
           float* __restrict__ out_h, float* __restrict__ out_c) {
    extern __shared__ __half smh[];
    uint32_t sbase = (uint32_t)__cvta_generic_to_shared(smh);
    const int BH = 18432;
    float* c0s  = (float*)((char*)smh + 71680);
    float* cufs = c0s + 512;
    float* bls  = cufs + 512;

    int tid = threadIdx.x, wid = tid >> 5, lane = tid & 31;
    int gid = lane >> 2, tig = lane & 3;
    int wr = wid >> 2, wc = wid & 3;
    int colBase = blockIdx.x * 128;
    int hgBase  = blockIdx.x * 32;

    int arow = (lane & 7) + ((lane >> 3) & 1) * 8;
    int ak   = (lane >> 4) * 8;
    int mrow = lane & 7;
    int mq   = lane >> 3;

#pragma unroll 8
    for (int it = tid; it < 2048; it += 256) {
        int r = it >> 4, q = (it & 15) * 8;
        cp16(sbase + ((BH + r * 136 + q) << 1),
             g_Mleaf + (size_t)(colBase + r) * 128 + q, 16);
    }
    if (tid < 128) {
        cp16((uint32_t)__cvta_generic_to_shared(c0s)  + tid * 16, c0      + tid * 4, 16);
        cp16((uint32_t)__cvta_generic_to_shared(cufs) + tid * 16, g_cuf   + tid * 4, 16);
        cp16((uint32_t)__cvta_generic_to_shared(bls)  + tid * 16, g_bleaf + tid * 4, 16);
    }
    CP_COMMIT();

    auto loadA = [&](int rt, int kc, int st) {
        const __half* src = g_emb16 + (size_t)rt * 128 * 128 + kc * 64;
#pragma unroll
        for (int it = tid; it < 1024; it += 256) {
            int r = it >> 3, q = (it & 7) * 8;
            cp16(sbase + ((st * 9216 + r * 72 + q) << 1), src + (size_t)r * 128 + q, 16);
        }
    };

    loadA(blockIdx.y, 0, 0);
    CP_COMMIT();

    for (int rt = blockIdx.y; rt < 512; rt += 74) {
        loadA(rt, 1, 1);
        CP_COMMIT();

        float acc[4][4][4];
#pragma unroll
        for (int mi = 0; mi < 4; mi++)
#pragma unroll
            for (int ni = 0; ni < 4; ni++)
#pragma unroll
                for (int q = 0; q < 4; q++) acc[mi][ni][q] = 0.f;

#pragma unroll
        for (int kc = 0; kc < 2; kc++) {
            CP_WAIT(1);
            __syncthreads();
#pragma unroll
            for (int ks = 0; ks < 64; ks += 16) {
                uint32_t a[4][4], b[4][2];
#pragma unroll
                for (int mi = 0; mi < 4; mi++)
                    ldm_x4(a[mi], sbase + ((kc * 9216 +
                        (wr * 64 + mi * 16 + arow) * 72 + ks + ak) << 1));
#pragma unroll
                for (int nip = 0; nip < 4; nip += 2)
                    ldm_x4v(b[nip][0], b[nip][1], b[nip + 1][0], b[nip + 1][1],
                            sbase + ((BH +
                        (wc * 32 + (nip + (mq >> 1)) * 8 + mrow) * 136 +
                        kc * 64 + ks + (mq & 1) * 8) << 1));
#pragma unroll
                for (int mi = 0; mi < 4; mi++)
#pragma unroll
                    for (int ni = 0; ni < 4; ni++)
                        mma16(acc[mi][ni], a[mi], b[ni]);
            }
            __syncthreads();
            if (kc == 0) {
                int nrt = rt + 74; if (nrt >= 512) nrt = 0;
                loadA(nrt, 0, 0);
                CP_COMMIT();
            }
        }

        // epilogue: 4 column quarters through A stage 1 (128x36 fp32)
        float (*Ysq)[36] = (float(*)[36])((char*)smh + 18432);
        int rowBaseG = rt * 128;
        int row = tid >> 1, hq = (tid & 1) * 4;
#pragma unroll
        for (int wq = 0; wq < 4; wq++) {
            if (wc == wq) {
#pragma unroll
                for (int mi = 0; mi < 4; mi++) {
                    int r0 = wr * 64 + mi * 16 + gid;
#pragma unroll
                    for (int ni = 0; ni < 4; ni++) {
                        int col = ni * 8 + tig * 2;
                        float bx = bls[colBase + wq * 32 + col];
                        float by = bls[colBase + wq * 32 + col + 1];
                        Ysq[r0][col]         = acc[mi][ni][0] + bx;
                        Ysq[r0][col + 1]     = acc[mi][ni][1] + by;
                        Ysq[r0 + 8][col]     = acc[mi][ni][2] + bx;
                        Ysq[r0 + 8][col + 1] = acc[mi][ni][3] + by;
                    }
                }
            }
            __syncthreads();
            float hb[4], cb[4];
#pragma unroll
            for (int j = 0; j < 4; j++) {
                int hl = hq + j;
                float4 v = *(const float4*)&Ysq[row][hl * 4];   // i, o, u, wf
                int hg = hgBase + wq * 8 + hl;
                float cc = sigf(v.x) * tanh_fast(v.z);
#pragma unroll
                for (int a = 0; a < 4; a++)
                    cc += sigf(v.w + cufs[a * 128 + hg]) * c0s[a * 128 + hg];
                hb[j] = sigf(v.y) * tanh_fast(cc);
                cb[j] = cc;
            }
            size_t ob = (size_t)(rowBaseG + row) * 128 + hgBase + wq * 8 + hq;
            *(float4*)(out_h + ob) = make_float4(hb[0], hb[1], hb[2], hb[3]);
            *(float4*)(out_c + ob) = make_float4(cb[0], cb[1], cb[2], cb[3]);
            __half2 p0 = __floats2half2_rn(hb[0], hb[1]);
            __half2 p1 = __floats2half2_rn(hb[2], hb[3]);
            uint2 u; u.x = *(const unsigned*)&p0; u.y = *(const unsigned*)&p1;
            *(uint2*)(g_h16 + ob) = u;
            __syncthreads();
        }
    }
}

// ---------------- fused inner: GEMM (128 x 112, K=640) + gates ----------------
// smem halves: A[2][128][72] 0..18432 ; B[2][112][72] 18432..34560.
// Ys reuse pitch 114. grid (8, ceil(n/128)). Warp tile 32 rows x 56 cols.
__global__ void __launch_bounds__(256, 2)
fused_inner(int embOff, int hOff, int outOff, const float* __restrict__ cprev,
            float* __restrict__ out_h, float* __restrict__ out_c, int n) {
    extern __shared__ __half smh[];
    uint32_t sbase = (uint32_t)__cvta_generic_to_shared(smh);
    const int BH = 18432;
    const __half* X16  = g_emb16 + (size_t)embOff * 128;
    const __half* Hp16 = g_h16   + (size_t)hOff   * 128;

    int tid = threadIdx.x, wid = tid >> 5, lane = tid & 31;
    int gid = lane >> 2, tig = lane & 3;
    int wr = wid >> 1;
    int wn = wid & 1;
    int rowBase = blockIdx.y * 128, colBase = blockIdx.x * 112;

    int arow = (lane & 7) + ((lane >> 3) & 1) * 8;
    int ak   = (lane >> 4) * 8;
    int bl   = lane & 15;
    int brow = bl & 7;
    int bk   = ((bl >> 3) & 1) * 8;
    int mrow = lane & 7;
    int mq   = lane >> 3;

    float acc[2][7][4];
#pragma unroll
    for (int mi = 0; mi < 2; mi++)
#pragma unroll
        for (int nt = 0; nt < 7; nt++)
#pragma unroll
            for (int q = 0; q < 4; q++) acc[mi][nt][q] = 0.f;

    auto loadAB = [&](int kc, int st) {
        int k0 = kc * 64;
        const __half* base; int pitch, koff;
        if (k0 < 128) { base = X16;  pitch = 128; koff = k0; }
        else          { base = Hp16; pitch = 512; koff = k0 - 128; }
        for (int it = tid; it < 1024; it += 256) {
            int r = it >> 3, q = (it & 7) * 8;
            int row = rowBase + r;
            cp16(sbase + ((st * 9216 + r * 72 + q) << 1),
                 base + (size_t)row * pitch + koff + q, (row < n) ? 16u : 0u);
        }
        for (int it = tid; it < 896; it += 256) {
            int r = it >> 3, q = (it & 7) * 8;
            cp16(sbase + ((BH + st * 8064 + r * 72 + q) << 1),
                 g_Mh + (size_t)(colBase + r) * 640 + k0 + q, 16);
        }
    };

    loadAB(0, 0);
    CP_COMMIT();

    for (int kc = 0; kc < 10; kc++) {
        int cur = kc & 1;
        if (kc < 9) {
            loadAB(kc + 1, cur ^ 1);
            CP_COMMIT();
            CP_WAIT(1);
        } else {
            CP_WAIT(0);
        }
        __syncthreads();
#pragma unroll
        for (int ks = 0; ks < 64; ks += 16) {
            uint32_t a[2][4], b[7][2];
#pragma unroll
            for (int mi = 0; mi < 2; mi++)
                ldm_x4(a[mi], sbase + ((cur * 9216 +
                    (wr * 32 + mi * 16 + arow) * 72 + ks + ak) << 1));
#pragma unroll
            for (int nip = 0; nip < 6; nip += 2)
                ldm_x4v(b[nip][0], b[nip][1], b[nip + 1][0], b[nip + 1][1],
                        sbase + ((BH + cur * 8064 +
                    (wn * 56 + (nip + (mq >> 1)) * 8 + mrow) * 72 +
                    ks + (mq & 1) * 8) << 1));
            ldm_x2(b[6], sbase + ((BH + cur * 8064 +
                (wn * 56 + 6 * 8 + brow) * 72 + ks + bk) << 1));
#pragma unroll
            for (int mi = 0; mi < 2; mi++)
#pragma unroll
                for (int nt = 0; nt < 7; nt++)
                    mma16(acc[mi][nt], a[mi], b[nt]);
        }
        __syncthreads();
    }

    // spill full Y tile (+bias) into reused smem, pitch 114 floats
    float (*Ys)[114] = (float(*)[114])smh;
#pragma unroll
    for (int mi = 0; mi < 2; mi++) {
        int r0 = wr * 32 + mi * 16 + gid;
#pragma unroll
        for (int nt = 0; nt < 7; nt++) {
            int col = wn * 56 + nt * 8 + tig * 2;
            float bx = g_bias[colBase + col], by = g_bias[colBase + col + 1];
            *(float2*)&Ys[r0][col]     = make_float2(acc[mi][nt][0] + bx, acc[mi][nt][1] + by);
            *(float2*)&Ys[r0 + 8][col] = make_float2(acc[mi][nt][2] + bx, acc[mi][nt][3] + by);
        }
    }
    __syncthreads();

    // gates: thread -> (row = tid>>1, 8 consecutive H)
    int row = tid >> 1, hhalf = tid & 1;
    int J = rowBase + row;
    if (J < n) {
        int hg0 = blockIdx.x * 16 + hhalf * 8;
        float4 cpv[4][2];
#pragma unroll
        for (int a = 0; a < 4; a++) {
            const float* cp = cprev + (size_t)(4 * J + a) * 128 + hg0;
            cpv[a][0] = *(const float4*)cp;
            cpv[a][1] = *(const float4*)(cp + 4);
        }
        float hb[8], cb[8];
#pragma unroll
        for (int j = 0; j < 8; j++) {
            const float* g = &Ys[row][(hhalf * 8 + j) * 7];
            float cc = sigf(g[0]) * tanh_fast(g[2]);
#pragma unroll
            for (int a = 0; a < 4; a++)
                cc += sigf(g[3 + a]) * ((const float*)&cpv[a][j >> 2])[j & 3];
            hb[j] = sigf(g[1]) * tanh_fast(cc);
            cb[j] = cc;
        }
        size_t ob = (size_t)(outOff + J) * 128 + hg0;
        *(float4*)(out_h + ob)     = make_float4(hb[0], hb[1], hb[2], hb[3]);
        *(float4*)(out_h + ob + 4) = make_float4(hb[4], hb[5], hb[6], hb[7]);
        *(float4*)(out_c + ob)     = make_float4(cb[0], cb[1], cb[2], cb[3]);
        *(float4*)(out_c + ob + 4) = make_float4(cb[4], cb[5], cb[6], cb[7]);
        __half2 p0 = __floats2half2_rn(hb[0], hb[1]);
        __half2 p1 = __floats2half2_rn(hb[2], hb[3]);
        __half2 p2 = __floats2half2_rn(hb[4], hb[5]);
        __half2 p3 = __floats2half2_rn(hb[6], hb[7]);
        uint4 u;
        u.x = *(const unsigned*)&p0; u.y = *(const unsigned*)&p1;
        u.z = *(const unsigned*)&p2; u.w = *(const unsigned*)&p3;
        *(uint4*)(g_h16 + ob) = u;
    }
}

// ---------------- launch ----------------
extern "C" void kernel_launch(void* const* d_in, const int* in_sizes, int n_in,
                              void* d_out, int out_size) {
    const float* emb    = (const float*)d_in[0];
    const float* W_iou  = (const float*)d_in[1];
    const float* b_iou  = (const float*)d_in[2];
    const float* U_iou  = (const float*)d_in[3];
    const float* b_uiou = (const float*)d_in[4];
    const float* W_f    = (const float*)d_in[5];
    const float* b_wf   = (const float*)d_in[6];
    const float* U_f    = (const float*)d_in[7];
    const float* b_uf   = (const float*)d_in[8];
    const float* h0     = (const float*)d_in[9];
    const float* c0     = (const float*)d_in[10];

    float* out_h = (float*)d_out;
    float* out_c = out_h + (size_t)NN * 128;

    cudaFuncSetAttribute(leaf_fused,  cudaFuncAttributeMaxDynamicSharedMemorySize, 77824);
    cudaFuncSetAttribute(fused_inner, cudaFuncAttributeMaxDynamicSharedMemorySize, 69120);

    prep_M_kernel<<<512, 256>>>(W_iou, U_iou, b_iou, b_uiou, W_f, U_f, b_wf, b_uf);
    emb2h_kernel<<<512, 256>>>(emb);
    prep_const_kernel<<<112, 256>>>(U_iou, b_iou, b_uiou, U_f, b_uf, h0, b_wf);

    const int lev_n[9] = {65536, 16384, 4096, 1024, 256, 64, 16, 4, 1};
    int offs[10];
    offs[0] = 0;
    for (int i = 0; i < 9; i++) offs[i + 1] = offs[i] + lev_n[i];

    // leaf level: persistent fused kernel (also fills g_h16[0:65536])
    leaf_fused<<<dim3(4, 74), 256, 77824>>>(c0, out_h, out_c);

    // inner levels 7..0: fused GEMM+gates
    for (int i = 1; i < 9; i++) {
        int n = lev_n[i];
        const float* Cp = out_c + (size_t)offs[i - 1] * 128;
        fused_inner<<<dim3(8, (n + 127) / 128), 256, 69120>>>(
            offs[i], offs[i - 1], offs[i], Cp, out_h, out_c, n);
    }
}